// round 8
// baseline (speedup 1.0000x reference)
#include <cuda_runtime.h>
#include <cuda_fp16.h>
#include <mma.h>
#include <math.h>
#include <stdint.h>

using namespace nvcuda;

// Problem constants (B=8192, B_pos=8192, D=1024, T=0.1)
#define B_N 8192
#define D_N 1024

// ---------------- scratch: total 384 MB, matching the proven R6 footprint ----------------
// g_S doubles as: fp32 score matrix, THEN per-row fp16 weight planes written in place:
//   row r as halves: base (half*)g_S + r*2*B_N ; [0..B_N) = WH, [B_N..2*B_N) = WL
static __device__ __align__(256) float  g_S[(size_t)B_N * B_N];      // 256 MB
static __device__ __align__(256) __half g_genH[(size_t)B_N * D_N];   // 16 MB
static __device__ __align__(256) __half g_genL[(size_t)B_N * D_N];   // 16 MB
static __device__ __align__(256) __half g_posH[(size_t)B_N * D_N];   // 16 MB
static __device__ __align__(256) __half g_posL[(size_t)B_N * D_N];   // 16 MB
static __device__ __align__(256) float g_attr[(size_t)B_N * D_N];    // 32 MB
static __device__ __align__(256) float g_rep[(size_t)B_N * D_N];     // 32 MB
static __device__ float g_gn[B_N];
static __device__ float g_pn[B_N];
static __device__ float g_part[B_N * 4];

// ---------------- reductions (proven) ----------------
__device__ __forceinline__ float warpSum(float v) {
#pragma unroll
    for (int o = 16; o > 0; o >>= 1) v += __shfl_xor_sync(0xffffffffu, v, o);
    return v;
}
__device__ __forceinline__ float warpMax(float v) {
#pragma unroll
    for (int o = 16; o > 0; o >>= 1) v = fmaxf(v, __shfl_xor_sync(0xffffffffu, v, o));
    return v;
}
__device__ float blockSum(float v) {
    __shared__ float s[33];
    int lane = threadIdx.x & 31, w = threadIdx.x >> 5;
    __syncthreads();
    v = warpSum(v);
    if (lane == 0) s[w] = v;
    __syncthreads();
    if (w == 0) {
        float t = (threadIdx.x < (blockDim.x >> 5)) ? s[threadIdx.x] : 0.f;
        t = warpSum(t);
        if (lane == 0) s[32] = t;
    }
    __syncthreads();
    return s[32];
}
__device__ float blockMax(float v) {
    __shared__ float s[33];
    int lane = threadIdx.x & 31, w = threadIdx.x >> 5;
    __syncthreads();
    v = warpMax(v);
    if (lane == 0) s[w] = v;
    __syncthreads();
    if (w == 0) {
        float t = (threadIdx.x < (blockDim.x >> 5)) ? s[threadIdx.x] : -INFINITY;
        t = warpMax(t);
        if (lane == 0) s[32] = t;
    }
    __syncthreads();
    return s[32];
}

// ---------------- K0: row squared norms (proven) ----------------
__global__ __launch_bounds__(256)
void norms_kernel(const float* __restrict__ gen, const float* __restrict__ pos) {
    int row = blockIdx.x;
    const float* src; float* dst;
    if (row < B_N) { src = gen + (size_t)row * D_N; dst = &g_gn[row]; }
    else           { src = pos + (size_t)(row - B_N) * D_N; dst = &g_pn[row - B_N]; }
    float s = 0.f;
    for (int c = threadIdx.x * 4; c < D_N; c += blockDim.x * 4) {
        float4 v = *(const float4*)(src + c);
        s += v.x * v.x + v.y * v.y + v.z * v.z + v.w * v.w;
    }
    s = blockSum(s);
    if (threadIdx.x == 0) *dst = s;
}

// ---------------- K1: fp16 hi/lo plane split (proven) ----------------
__global__ __launch_bounds__(256)
void split16(const float* __restrict__ gen, const float* __restrict__ pos) {
    const size_t total = (size_t)B_N * D_N;
    for (size_t idx = (size_t)blockIdx.x * blockDim.x + threadIdx.x; idx < total;
         idx += (size_t)gridDim.x * blockDim.x) {
        float x = gen[idx];
        __half h = __float2half(x);
        g_genH[idx] = h;
        g_genL[idx] = __float2half(x - __half2float(h));
        float y = pos[idx];
        __half hp = __float2half(y);
        g_posH[idx] = hp;
        g_posL[idx] = __float2half(y - __half2float(hp));
    }
}

// ---------------- K2: score GEMM via WMMA (byte-identical to proven R6) ----------------
#define LDS 72                 // padded smem stride in halves (A tiles & score B tiles)
#define TILE_H (128 * LDS)     // 9216 halves per tile

__global__ __launch_bounds__(256)
void score_wmma(int b_is_gen) {
    __shared__ __align__(32) __half sh[2 * TILE_H];   // 36,864 B
    __half* shA = sh;
    __half* shB = sh + TILE_H;

    const int tid = threadIdx.x, lane = tid & 31, wid = tid >> 5;
    const int wm = (wid & 3) * 32, wn = (wid >> 2) * 64;
    const int m0 = blockIdx.y * 128, n0 = blockIdx.x * 128;

    const __half* segA[3] = { g_genH, g_genH, g_genL };
    const __half* segB[3];
    if (b_is_gen) { segB[0] = g_genH; segB[1] = g_genL; segB[2] = g_genH; }
    else          { segB[0] = g_posH; segB[1] = g_posL; segB[2] = g_posH; }

    wmma::fragment<wmma::accumulator, 16, 16, 16, float> cfr[2][4];
#pragma unroll
    for (int i = 0; i < 2; i++)
#pragma unroll
        for (int j = 0; j < 4; j++) wmma::fill_fragment(cfr[i][j], 0.f);

    for (int seg = 0; seg < 3; seg++) {
        const __half* A = segA[seg];
        const __half* B = segB[seg];
        for (int t = 0; t < D_N / 64; t++) {
            __syncthreads();
#pragma unroll
            for (int i = 0; i < 4; i++) {
                int f = i * 256 + tid, r = f >> 3, cc = f & 7;
                *(uint4*)(shA + r * LDS + cc * 8) =
                    *(const uint4*)(A + (size_t)(m0 + r) * D_N + t * 64 + cc * 8);
                *(uint4*)(shB + r * LDS + cc * 8) =
                    *(const uint4*)(B + (size_t)(n0 + r) * D_N + t * 64 + cc * 8);
            }
            __syncthreads();
#pragma unroll
            for (int ks = 0; ks < 4; ks++) {
                wmma::fragment<wmma::matrix_a, 16, 16, 16, __half, wmma::row_major> afr[2];
                wmma::fragment<wmma::matrix_b, 16, 16, 16, __half, wmma::col_major> bfr[4];
#pragma unroll
                for (int i = 0; i < 2; i++)
                    wmma::load_matrix_sync(afr[i], shA + (wm + i * 16) * LDS + ks * 16, LDS);
#pragma unroll
                for (int j = 0; j < 4; j++)
                    wmma::load_matrix_sync(bfr[j], shB + (wn + j * 16) * LDS + ks * 16, LDS);
#pragma unroll
                for (int i = 0; i < 2; i++)
#pragma unroll
                    for (int j = 0; j < 4; j++)
                        wmma::mma_sync(cfr[i][j], afr[i], bfr[j], cfr[i][j]);
            }
        }
    }

    __syncthreads();
    float* patch = ((float*)sh) + wid * 256;
    const float* bnp = b_is_gen ? g_gn : g_pn;
#pragma unroll
    for (int i = 0; i < 2; i++) {
#pragma unroll
        for (int j = 0; j < 4; j++) {
            wmma::store_matrix_sync(patch, cfr[i][j], 16, wmma::mem_row_major);
            __syncwarp();
            const int pr = lane >> 1, pc = (lane & 1) * 8;
            const int row = m0 + wm + i * 16 + pr;
            const int colb = n0 + wn + j * 16 + pc;
            const float an = g_gn[row];
            float4 bn0 = *(const float4*)(bnp + colb);
            float4 bn1 = *(const float4*)(bnp + colb + 4);
            const float* p = patch + pr * 16 + pc;
            float bns[8] = {bn0.x, bn0.y, bn0.z, bn0.w, bn1.x, bn1.y, bn1.z, bn1.w};
            float o[8];
#pragma unroll
            for (int e = 0; e < 8; e++) {
                float d2 = fmaxf(an + bns[e] - 2.f * p[e], 0.f);
                o[e] = -10.f * sqrtf(d2);
            }
            float* dst = g_S + (size_t)row * B_N + colb;
            *(float4*)dst       = make_float4(o[0], o[1], o[2], o[3]);
            *(float4*)(dst + 4) = make_float4(o[4], o[5], o[6], o[7]);
            __syncwarp();
        }
    }
}

// ---------------- K3: row softmax -> fp16 hi/lo weight planes IN PLACE in g_S ----------------
__global__ __launch_bounds__(256)
void softmax_w16(int mask_diag) {
    __shared__ float sm[B_N];
    int row = blockIdx.x;
    const float* Srow = g_S + (size_t)row * B_N;
    float mx = -INFINITY;
    for (int j = threadIdx.x; j < B_N; j += blockDim.x) {
        float v = Srow[j];
        if (mask_diag && j == row) v = -INFINITY;
        sm[j] = v;
        mx = fmaxf(mx, v);
    }
    mx = blockMax(mx);
    float sum = 0.f;
    for (int j = threadIdx.x; j < B_N; j += blockDim.x) {
        float e = expf(sm[j] - mx);
        sm[j] = e;
        sum += e;
    }
    sum = blockSum(sum);
    float inv = 1.f / sum;
    // entire fp32 row is now cached in smem; overwrite the same 32KB with half planes
    __syncthreads();
    __half* WH = (__half*)g_S + (size_t)row * (2 * B_N);
    __half* WL = WH + B_N;
    for (int j = threadIdx.x; j < B_N; j += blockDim.x) {
        float w = sm[j] * inv;
        __half h = __float2half(w);
        WH[j] = h;
        WL[j] = __float2half(w - __half2float(h));
    }
}

// ---------------- K4: wavg GEMM via WMMA: out = W . P - sub ----------------
// A = W planes in g_S: row-major [m][k], ld 2*B_N (WH at +0, WL at +B_N)
// B = P planes (pos/gen H/L as stored): row-major [k][n], ld D_N -> wmma row_major B fragment
#define LDSB 136                 // padded smem stride for B tiles (128 + 8 halves)

__global__ __launch_bounds__(256)
void wavg_wmma(const float* __restrict__ sub, int to_rep) {
    __shared__ __align__(32) __half shA[128 * LDS];   // 18,432 B
    __shared__ __align__(32) __half shB[64 * LDSB];   // 17,408 B

    const int tid = threadIdx.x, lane = tid & 31, wid = tid >> 5;
    const int wm = (wid & 3) * 32, wn = (wid >> 2) * 64;
    const int m0 = blockIdx.y * 128, n0 = blockIdx.x * 128;

    const __half* WH = (const __half*)g_S;          // ld 2*B_N
    const __half* WL = (const __half*)g_S + B_N;
    const __half* segA[3] = { WH, WH, WL };
    const __half* segB[3];
    if (to_rep) { segB[0] = g_genH; segB[1] = g_genL; segB[2] = g_genH; }
    else        { segB[0] = g_posH; segB[1] = g_posL; segB[2] = g_posH; }

    wmma::fragment<wmma::accumulator, 16, 16, 16, float> cfr[2][4];
#pragma unroll
    for (int i = 0; i < 2; i++)
#pragma unroll
        for (int j = 0; j < 4; j++) wmma::fill_fragment(cfr[i][j], 0.f);

    for (int seg = 0; seg < 3; seg++) {
        const __half* A = segA[seg];
        const __half* B = segB[seg];
        for (int t = 0; t < B_N / 64; t++) {
            __syncthreads();
            // A tile: 128 rows x 64 k (k contiguous), ld 2*B_N
#pragma unroll
            for (int i = 0; i < 4; i++) {
                int f = i * 256 + tid, r = f >> 3, cc = f & 7;
                *(uint4*)(shA + r * LDS + cc * 8) =
                    *(const uint4*)(A + (size_t)(m0 + r) * (2 * B_N) + t * 64 + cc * 8);
            }
            // B tile: 64 k-rows x 128 n (n contiguous), ld D_N
#pragma unroll
            for (int i = 0; i < 4; i++) {
                int f = i * 256 + tid, r = f >> 4, cc = f & 15;
                *(uint4*)(shB + r * LDSB + cc * 8) =
                    *(const uint4*)(B + (size_t)(t * 64 + r) * D_N + n0 + cc * 8);
            }
            __syncthreads();
#pragma unroll
            for (int ks = 0; ks < 4; ks++) {
                wmma::fragment<wmma::matrix_a, 16, 16, 16, __half, wmma::row_major> afr[2];
                wmma::fragment<wmma::matrix_b, 16, 16, 16, __half, wmma::row_major> bfr[4];
#pragma unroll
                for (int i = 0; i < 2; i++)
                    wmma::load_matrix_sync(afr[i], shA + (wm + i * 16) * LDS + ks * 16, LDS);
#pragma unroll
                for (int j = 0; j < 4; j++)
                    wmma::load_matrix_sync(bfr[j], shB + (ks * 16) * LDSB + wn + j * 16, LDSB);
#pragma unroll
                for (int i = 0; i < 2; i++)
#pragma unroll
                    for (int j = 0; j < 4; j++)
                        wmma::mma_sync(cfr[i][j], afr[i], bfr[j], cfr[i][j]);
            }
        }
    }

    float* outp = to_rep ? g_rep : g_attr;
    __syncthreads();
    float* patch = ((float*)shA) + wid * 256;    // 8 KB total, fits in shA
#pragma unroll
    for (int i = 0; i < 2; i++) {
#pragma unroll
        for (int j = 0; j < 4; j++) {
            wmma::store_matrix_sync(patch, cfr[i][j], 16, wmma::mem_row_major);
            __syncwarp();
            const int pr = lane >> 1, pc = (lane & 1) * 8;
            const int row = m0 + wm + i * 16 + pr;
            const int colb = n0 + wn + j * 16 + pc;
            const float* p = patch + pr * 16 + pc;
            size_t base = (size_t)row * D_N + colb;
            float4 s0 = *(const float4*)(sub + base);
            float4 s1 = *(const float4*)(sub + base + 4);
            *(float4*)(outp + base)     = make_float4(p[0] - s0.x, p[1] - s0.y,
                                                      p[2] - s0.z, p[3] - s0.w);
            *(float4*)(outp + base + 4) = make_float4(p[4] - s1.x, p[5] - s1.y,
                                                      p[6] - s1.z, p[7] - s1.w);
            __syncwarp();
        }
    }
}

// ---------------- K5/K6: final reductions (proven) ----------------
__global__ __launch_bounds__(256)
void row_reduce() {
    int row = blockIdx.x;
    const float* a = g_attr + (size_t)row * D_N;
    const float* r = g_rep + (size_t)row * D_N;
    float sa = 0.f, sr = 0.f, sd = 0.f;
    for (int c = threadIdx.x * 4; c < D_N; c += blockDim.x * 4) {
        float4 av = *(const float4*)(a + c);
        float4 rv = *(const float4*)(r + c);
        float dx = av.x - rv.x, dy = av.y - rv.y, dz = av.z - rv.z, dw = av.w - rv.w;
        sa += av.x * av.x + av.y * av.y + av.z * av.z + av.w * av.w;
        sr += rv.x * rv.x + rv.y * rv.y + rv.z * rv.z + rv.w * rv.w;
        sd += dx * dx + dy * dy + dz * dz + dw * dw;
    }
    sa = blockSum(sa); sr = blockSum(sr); sd = blockSum(sd);
    if (threadIdx.x == 0) {
        g_part[row * 4 + 0] = sd;
        g_part[row * 4 + 1] = sqrtf(sd);
        g_part[row * 4 + 2] = sqrtf(sa);
        g_part[row * 4 + 3] = sqrtf(sr);
    }
}

__global__ __launch_bounds__(256)
void final_reduce(float* __restrict__ out) {
    float s0 = 0.f, s1 = 0.f, s2 = 0.f, s3 = 0.f;
    for (int i = threadIdx.x; i < B_N; i += blockDim.x) {
        s0 += g_part[i * 4 + 0]; s1 += g_part[i * 4 + 1];
        s2 += g_part[i * 4 + 2]; s3 += g_part[i * 4 + 3];
    }
    s0 = blockSum(s0); s1 = blockSum(s1); s2 = blockSum(s2); s3 = blockSum(s3);
    if (threadIdx.x == 0) {
        out[0] = s0 / ((float)B_N * (float)D_N);
        out[1] = s1 / (float)B_N;
        out[2] = s2 / (float)B_N;
        out[3] = s3 / (float)B_N;
    }
}

// ---------------- launch ----------------
extern "C" void kernel_launch(void* const* d_in, const int* in_sizes, int n_in,
                              void* d_out, int out_size) {
    const float* gen = (const float*)d_in[0];
    const float* pos = (const float*)d_in[1];
    float* out = (float*)d_out;

    norms_kernel<<<2 * B_N, 256>>>(gen, pos);
    split16<<<4096, 256>>>(gen, pos);

    // Attraction: scores(gen,pos) -> softmax(W in-place) -> W@pos - gen
    score_wmma<<<dim3(64, 64), 256>>>(0);
    softmax_w16<<<B_N, 256>>>(0);
    wavg_wmma<<<dim3(D_N / 128, B_N / 128), 256>>>(gen, 0);

    // Repulsion: scores(gen,gen) diag-masked -> softmax -> W@gen - gen
    score_wmma<<<dim3(64, 64), 256>>>(1);
    softmax_w16<<<B_N, 256>>>(1);
    wavg_wmma<<<dim3(D_N / 128, B_N / 128), 256>>>(gen, 1);

    row_reduce<<<B_N, 256>>>();
    final_reduce<<<1, 256>>>(out);
}

// round 10
// speedup vs baseline: 1.5217x; 1.5217x over previous
#include <cuda_runtime.h>
#include <cuda_fp16.h>
#include <mma.h>
#include <math.h>
#include <stdint.h>

using namespace nvcuda;

// Problem constants (B=8192, B_pos=8192, D=1024, T=0.1)
#define B_N 8192
#define D_N 1024

// ---------------- scratch: EXACTLY the proven 384 MB set from R8 ----------------
// g_S doubles as fp32 score matrix, then per-row fp16 weight planes in place:
//   row r as halves: (half*)g_S + r*2*B_N ; [0..B_N)=WH, [B_N..2*B_N)=WL
static __device__ __align__(256) float  g_S[(size_t)B_N * B_N];      // 256 MB
static __device__ __align__(256) __half g_genH[(size_t)B_N * D_N];   // 16 MB
static __device__ __align__(256) __half g_genL[(size_t)B_N * D_N];   // 16 MB
static __device__ __align__(256) __half g_posH[(size_t)B_N * D_N];   // 16 MB
static __device__ __align__(256) __half g_posL[(size_t)B_N * D_N];   // 16 MB
static __device__ __align__(256) float g_attr[(size_t)B_N * D_N];    // 32 MB
static __device__ __align__(256) float g_rep[(size_t)B_N * D_N];     // 32 MB
static __device__ float g_gn[B_N];
static __device__ float g_pn[B_N];
static __device__ float g_part[B_N * 4];

// ---------------- reductions (proven) ----------------
__device__ __forceinline__ float warpSum(float v) {
#pragma unroll
    for (int o = 16; o > 0; o >>= 1) v += __shfl_xor_sync(0xffffffffu, v, o);
    return v;
}
__device__ __forceinline__ float warpMax(float v) {
#pragma unroll
    for (int o = 16; o > 0; o >>= 1) v = fmaxf(v, __shfl_xor_sync(0xffffffffu, v, o));
    return v;
}
__device__ float blockSum(float v) {
    __shared__ float s[33];
    int lane = threadIdx.x & 31, w = threadIdx.x >> 5;
    __syncthreads();
    v = warpSum(v);
    if (lane == 0) s[w] = v;
    __syncthreads();
    if (w == 0) {
        float t = (threadIdx.x < (blockDim.x >> 5)) ? s[threadIdx.x] : 0.f;
        t = warpSum(t);
        if (lane == 0) s[32] = t;
    }
    __syncthreads();
    return s[32];
}
__device__ float blockMax(float v) {
    __shared__ float s[33];
    int lane = threadIdx.x & 31, w = threadIdx.x >> 5;
    __syncthreads();
    v = warpMax(v);
    if (lane == 0) s[w] = v;
    __syncthreads();
    if (w == 0) {
        float t = (threadIdx.x < (blockDim.x >> 5)) ? s[threadIdx.x] : -INFINITY;
        t = warpMax(t);
        if (lane == 0) s[32] = t;
    }
    __syncthreads();
    return s[32];
}

// ---------------- K0: row squared norms (proven) ----------------
__global__ __launch_bounds__(256)
void norms_kernel(const float* __restrict__ gen, const float* __restrict__ pos) {
    int row = blockIdx.x;
    const float* src; float* dst;
    if (row < B_N) { src = gen + (size_t)row * D_N; dst = &g_gn[row]; }
    else           { src = pos + (size_t)(row - B_N) * D_N; dst = &g_pn[row - B_N]; }
    float s = 0.f;
    for (int c = threadIdx.x * 4; c < D_N; c += blockDim.x * 4) {
        float4 v = *(const float4*)(src + c);
        s += v.x * v.x + v.y * v.y + v.z * v.z + v.w * v.w;
    }
    s = blockSum(s);
    if (threadIdx.x == 0) *dst = s;
}

// ---------------- K1: fp16 hi/lo plane split (proven) ----------------
__global__ __launch_bounds__(256)
void split16(const float* __restrict__ gen, const float* __restrict__ pos) {
    const size_t total = (size_t)B_N * D_N;
    for (size_t idx = (size_t)blockIdx.x * blockDim.x + threadIdx.x; idx < total;
         idx += (size_t)gridDim.x * blockDim.x) {
        float x = gen[idx];
        __half h = __float2half(x);
        g_genH[idx] = h;
        g_genL[idx] = __float2half(x - __half2float(h));
        float y = pos[idx];
        __half hp = __float2half(y);
        g_posH[idx] = hp;
        g_posL[idx] = __float2half(y - __half2float(hp));
    }
}

// ---------------- K2: score GEMM via WMMA (proven, unchanged) ----------------
#define LDS 72                 // padded smem stride in halves
#define TILE_H (128 * LDS)     // 9216 halves per tile

__global__ __launch_bounds__(256)
void score_wmma(int b_is_gen) {
    __shared__ __align__(32) __half sh[2 * TILE_H];   // 36,864 B
    __half* shA = sh;
    __half* shB = sh + TILE_H;

    const int tid = threadIdx.x, lane = tid & 31, wid = tid >> 5;
    const int wm = (wid & 3) * 32, wn = (wid >> 2) * 64;
    const int m0 = blockIdx.y * 128, n0 = blockIdx.x * 128;

    const __half* segA[3] = { g_genH, g_genH, g_genL };
    const __half* segB[3];
    if (b_is_gen) { segB[0] = g_genH; segB[1] = g_genL; segB[2] = g_genH; }
    else          { segB[0] = g_posH; segB[1] = g_posL; segB[2] = g_posH; }

    wmma::fragment<wmma::accumulator, 16, 16, 16, float> cfr[2][4];
#pragma unroll
    for (int i = 0; i < 2; i++)
#pragma unroll
        for (int j = 0; j < 4; j++) wmma::fill_fragment(cfr[i][j], 0.f);

    for (int seg = 0; seg < 3; seg++) {
        const __half* A = segA[seg];
        const __half* B = segB[seg];
        for (int t = 0; t < D_N / 64; t++) {
            __syncthreads();
#pragma unroll
            for (int i = 0; i < 4; i++) {
                int f = i * 256 + tid, r = f >> 3, cc = f & 7;
                *(uint4*)(shA + r * LDS + cc * 8) =
                    *(const uint4*)(A + (size_t)(m0 + r) * D_N + t * 64 + cc * 8);
                *(uint4*)(shB + r * LDS + cc * 8) =
                    *(const uint4*)(B + (size_t)(n0 + r) * D_N + t * 64 + cc * 8);
            }
            __syncthreads();
#pragma unroll
            for (int ks = 0; ks < 4; ks++) {
                wmma::fragment<wmma::matrix_a, 16, 16, 16, __half, wmma::row_major> afr[2];
                wmma::fragment<wmma::matrix_b, 16, 16, 16, __half, wmma::col_major> bfr[4];
#pragma unroll
                for (int i = 0; i < 2; i++)
                    wmma::load_matrix_sync(afr[i], shA + (wm + i * 16) * LDS + ks * 16, LDS);
#pragma unroll
                for (int j = 0; j < 4; j++)
                    wmma::load_matrix_sync(bfr[j], shB + (wn + j * 16) * LDS + ks * 16, LDS);
#pragma unroll
                for (int i = 0; i < 2; i++)
#pragma unroll
                    for (int j = 0; j < 4; j++)
                        wmma::mma_sync(cfr[i][j], afr[i], bfr[j], cfr[i][j]);
            }
        }
    }

    __syncthreads();
    float* patch = ((float*)sh) + wid * 256;
    const float* bnp = b_is_gen ? g_gn : g_pn;
#pragma unroll
    for (int i = 0; i < 2; i++) {
#pragma unroll
        for (int j = 0; j < 4; j++) {
            wmma::store_matrix_sync(patch, cfr[i][j], 16, wmma::mem_row_major);
            __syncwarp();
            const int pr = lane >> 1, pc = (lane & 1) * 8;
            const int row = m0 + wm + i * 16 + pr;
            const int colb = n0 + wn + j * 16 + pc;
            const float an = g_gn[row];
            float4 bn0 = *(const float4*)(bnp + colb);
            float4 bn1 = *(const float4*)(bnp + colb + 4);
            const float* p = patch + pr * 16 + pc;
            float bns[8] = {bn0.x, bn0.y, bn0.z, bn0.w, bn1.x, bn1.y, bn1.z, bn1.w};
            float o[8];
#pragma unroll
            for (int e = 0; e < 8; e++) {
                float d2 = fmaxf(an + bns[e] - 2.f * p[e], 0.f);
                o[e] = -10.f * sqrtf(d2);
            }
            float* dst = g_S + (size_t)row * B_N + colb;
            *(float4*)dst       = make_float4(o[0], o[1], o[2], o[3]);
            *(float4*)(dst + 4) = make_float4(o[4], o[5], o[6], o[7]);
            __syncwarp();
        }
    }
}

// ---------------- K3: row softmax -> fp16 hi/lo weight planes in place (proven R8) ----------------
__global__ __launch_bounds__(256)
void softmax_w16(int mask_diag) {
    __shared__ float sm[B_N];
    int row = blockIdx.x;
    const float* Srow = g_S + (size_t)row * B_N;
    float mx = -INFINITY;
    for (int j = threadIdx.x; j < B_N; j += blockDim.x) {
        float v = Srow[j];
        if (mask_diag && j == row) v = -INFINITY;
        sm[j] = v;
        mx = fmaxf(mx, v);
    }
    mx = blockMax(mx);
    float sum = 0.f;
    for (int j = threadIdx.x; j < B_N; j += blockDim.x) {
        float e = expf(sm[j] - mx);
        sm[j] = e;
        sum += e;
    }
    sum = blockSum(sum);
    float inv = 1.f / sum;
    __syncthreads();
    __half* WH = (__half*)g_S + (size_t)row * (2 * B_N);
    __half* WL = WH + B_N;
    for (int j = threadIdx.x; j < B_N; j += blockDim.x) {
        float w = sm[j] * inv;
        __half h = __float2half(w);
        WH[j] = h;
        WL[j] = __float2half(w - __half2float(h));
    }
}

// ---------------- K4: wavg GEMM, FLIPPED: out^T = P^T . W^T ----------------
// out[m][nn] = sum_k W[m][k] * P[k][nn]
//   matrix_a (2 frags) = P^T (nn x k): col_major from smem [k][nn] tile, ld LDSP (trans path, L2-hot data)
//   matrix_b (4 frags) = W^T (k x m):  col_major from smem [m][k] tile, ld LDS  (PROVEN fast path)
// W tiles (DRAM-heavy) are register-prefetched one iteration ahead.
#define LDSP 136

__global__ __launch_bounds__(256)
void wavg_wmma(const float* __restrict__ sub, int to_rep) {
    __shared__ __align__(32) __half shW[128 * LDS];    // 18,432 B : W^T source [m][k]
    __shared__ __align__(32) __half shP[64 * LDSP];    // 17,408 B : P^T source [k][nn]

    const int tid = threadIdx.x, lane = tid & 31, wid = tid >> 5;
    const int w_nn = (wid & 3) * 32;     // nn (D) direction: 4 warps
    const int w_m  = (wid >> 2) * 64;    // m  (B) direction: 2 warps
    const int n0 = blockIdx.x * 128;     // D blocks (8)  -- consecutive CTAs share m0 via y? no:
    const int m0 = blockIdx.y * 128;     // B blocks (64); x fastest => consecutive CTAs share m0's W tiles

    const __half* WHp = (const __half*)g_S;
    const __half* WLp = (const __half*)g_S + B_N;
    const __half* segW[3] = { WHp, WHp, WLp };
    const __half* segP[3];
    if (to_rep) { segP[0] = g_genH; segP[1] = g_genL; segP[2] = g_genH; }
    else        { segP[0] = g_posH; segP[1] = g_posL; segP[2] = g_posH; }

    wmma::fragment<wmma::accumulator, 16, 16, 16, float> cfr[2][4];   // [nn][m]
#pragma unroll
    for (int i = 0; i < 2; i++)
#pragma unroll
        for (int j = 0; j < 4; j++) wmma::fill_fragment(cfr[i][j], 0.f);

    const int NT = B_N / 64;   // 128 k-tiles per segment
    for (int seg = 0; seg < 3; seg++) {
        const __half* Wp = segW[seg];
        const __half* Pp = segP[seg];
        uint4 wreg[4];
#pragma unroll
        for (int i = 0; i < 4; i++) {                     // preload t=0 W tile
            int f = i * 256 + tid, r = f >> 3, cc = f & 7;
            wreg[i] = *(const uint4*)(Wp + (size_t)(m0 + r) * (2 * B_N) + cc * 8);
        }
        for (int t = 0; t < NT; t++) {
            __syncthreads();   // WAR: previous compute done with smem
#pragma unroll
            for (int i = 0; i < 4; i++) {                 // commit prefetched W tile
                int f = i * 256 + tid, r = f >> 3, cc = f & 7;
                *(uint4*)(shW + r * LDS + cc * 8) = wreg[i];
            }
#pragma unroll
            for (int i = 0; i < 4; i++) {                 // P tile (L2-hot): load directly
                int f = i * 256 + tid, r = f >> 4, cc = f & 15;
                *(uint4*)(shP + r * LDSP + cc * 8) =
                    *(const uint4*)(Pp + (size_t)(t * 64 + r) * D_N + n0 + cc * 8);
            }
            __syncthreads();
            if (t + 1 < NT) {                             // prefetch next W tile (hides DRAM)
#pragma unroll
                for (int i = 0; i < 4; i++) {
                    int f = i * 256 + tid, r = f >> 3, cc = f & 7;
                    wreg[i] = *(const uint4*)(Wp + (size_t)(m0 + r) * (2 * B_N) + (t + 1) * 64 + cc * 8);
                }
            }
#pragma unroll
            for (int ks = 0; ks < 4; ks++) {
                wmma::fragment<wmma::matrix_a, 16, 16, 16, __half, wmma::col_major> afr[2];
                wmma::fragment<wmma::matrix_b, 16, 16, 16, __half, wmma::col_major> bfr[4];
#pragma unroll
                for (int i = 0; i < 2; i++)   // P^T (nn,k) tile origin: ptr[k*LDSP + nn]
                    wmma::load_matrix_sync(afr[i], shP + (ks * 16) * LDSP + w_nn + i * 16, LDSP);
#pragma unroll
                for (int j = 0; j < 4; j++)   // W^T (k,m) tile origin: ptr[m*LDS + k]  (proven path)
                    wmma::load_matrix_sync(bfr[j], shW + (w_m + j * 16) * LDS + ks * 16, LDS);
#pragma unroll
                for (int i = 0; i < 2; i++)
#pragma unroll
                    for (int j = 0; j < 4; j++)
                        wmma::mma_sync(cfr[i][j], afr[i], bfr[j], cfr[i][j]);
            }
        }
    }

    // epilogue: cfr[i][j] is 16(nn) x 16(m); store col_major -> patch[m_local*16 + nn_local]
    float* outp = to_rep ? g_rep : g_attr;
    __syncthreads();
    float* patch = ((float*)shW) + wid * 256;
#pragma unroll
    for (int i = 0; i < 2; i++) {
#pragma unroll
        for (int j = 0; j < 4; j++) {
            wmma::store_matrix_sync(patch, cfr[i][j], 16, wmma::mem_col_major);
            __syncwarp();
            const int pr = lane >> 1, pc = (lane & 1) * 8;     // pr = m_local, pc = nn_local base
            const int m  = m0 + w_m + j * 16 + pr;
            const int nn = n0 + w_nn + i * 16 + pc;
            const float* p = patch + pr * 16 + pc;
            size_t base = (size_t)m * D_N + nn;
            float4 s0 = *(const float4*)(sub + base);
            float4 s1 = *(const float4*)(sub + base + 4);
            *(float4*)(outp + base)     = make_float4(p[0] - s0.x, p[1] - s0.y,
                                                      p[2] - s0.z, p[3] - s0.w);
            *(float4*)(outp + base + 4) = make_float4(p[4] - s1.x, p[5] - s1.y,
                                                      p[6] - s1.z, p[7] - s1.w);
            __syncwarp();
        }
    }
}

// ---------------- K5/K6: final reductions (proven) ----------------
__global__ __launch_bounds__(256)
void row_reduce() {
    int row = blockIdx.x;
    const float* a = g_attr + (size_t)row * D_N;
    const float* r = g_rep + (size_t)row * D_N;
    float sa = 0.f, sr = 0.f, sd = 0.f;
    for (int c = threadIdx.x * 4; c < D_N; c += blockDim.x * 4) {
        float4 av = *(const float4*)(a + c);
        float4 rv = *(const float4*)(r + c);
        float dx = av.x - rv.x, dy = av.y - rv.y, dz = av.z - rv.z, dw = av.w - rv.w;
        sa += av.x * av.x + av.y * av.y + av.z * av.z + av.w * av.w;
        sr += rv.x * rv.x + rv.y * rv.y + rv.z * rv.z + rv.w * rv.w;
        sd += dx * dx + dy * dy + dz * dz + dw * dw;
    }
    sa = blockSum(sa); sr = blockSum(sr); sd = blockSum(sd);
    if (threadIdx.x == 0) {
        g_part[row * 4 + 0] = sd;
        g_part[row * 4 + 1] = sqrtf(sd);
        g_part[row * 4 + 2] = sqrtf(sa);
        g_part[row * 4 + 3] = sqrtf(sr);
    }
}

__global__ __launch_bounds__(256)
void final_reduce(float* __restrict__ out) {
    float s0 = 0.f, s1 = 0.f, s2 = 0.f, s3 = 0.f;
    for (int i = threadIdx.x; i < B_N; i += blockDim.x) {
        s0 += g_part[i * 4 + 0]; s1 += g_part[i * 4 + 1];
        s2 += g_part[i * 4 + 2]; s3 += g_part[i * 4 + 3];
    }
    s0 = blockSum(s0); s1 = blockSum(s1); s2 = blockSum(s2); s3 = blockSum(s3);
    if (threadIdx.x == 0) {
        out[0] = s0 / ((float)B_N * (float)D_N);
        out[1] = s1 / (float)B_N;
        out[2] = s2 / (float)B_N;
        out[3] = s3 / (float)B_N;
    }
}

// ---------------- launch ----------------
extern "C" void kernel_launch(void* const* d_in, const int* in_sizes, int n_in,
                              void* d_out, int out_size) {
    const float* gen = (const float*)d_in[0];
    const float* pos = (const float*)d_in[1];
    float* out = (float*)d_out;

    norms_kernel<<<2 * B_N, 256>>>(gen, pos);
    split16<<<4096, 256>>>(gen, pos);

    // Attraction: scores(gen,pos) -> softmax(W in place) -> W@pos - gen
    score_wmma<<<dim3(64, 64), 256>>>(0);
    softmax_w16<<<B_N, 256>>>(0);
    wavg_wmma<<<dim3(8, 64), 256>>>(gen, 0);

    // Repulsion: scores(gen,gen) diag-masked -> softmax -> W@gen - gen
    score_wmma<<<dim3(64, 64), 256>>>(1);
    softmax_w16<<<B_N, 256>>>(1);
    wavg_wmma<<<dim3(8, 64), 256>>>(gen, 1);

    row_reduce<<<B_N, 256>>>();
    final_reduce<<<1, 256>>>(out);
}

// round 11
// speedup vs baseline: 1.7964x; 1.1805x over previous
#include <cuda_runtime.h>
#include <cuda_fp16.h>
#include <cuda_pipeline.h>
#include <mma.h>
#include <math.h>
#include <stdint.h>

using namespace nvcuda;

// Problem constants (B=8192, B_pos=8192, D=1024, T=0.1)
#define B_N 8192
#define D_N 1024

// ---------------- scratch: EXACTLY the proven 384 MB set ----------------
// g_S doubles as fp32 score matrix, then per-row fp16 weight planes in place:
//   row r as halves: (half*)g_S + r*2*B_N ; [0..B_N)=WH, [B_N..2*B_N)=WL
static __device__ __align__(256) float  g_S[(size_t)B_N * B_N];      // 256 MB
static __device__ __align__(256) __half g_genH[(size_t)B_N * D_N];   // 16 MB
static __device__ __align__(256) __half g_genL[(size_t)B_N * D_N];   // 16 MB
static __device__ __align__(256) __half g_posH[(size_t)B_N * D_N];   // 16 MB
static __device__ __align__(256) __half g_posL[(size_t)B_N * D_N];   // 16 MB
static __device__ __align__(256) float g_attr[(size_t)B_N * D_N];    // 32 MB
static __device__ __align__(256) float g_rep[(size_t)B_N * D_N];     // 32 MB
static __device__ float g_gn[B_N];
static __device__ float g_pn[B_N];
static __device__ float g_part[B_N * 4];

// ---------------- reductions (proven) ----------------
__device__ __forceinline__ float warpSum(float v) {
#pragma unroll
    for (int o = 16; o > 0; o >>= 1) v += __shfl_xor_sync(0xffffffffu, v, o);
    return v;
}
__device__ __forceinline__ float warpMax(float v) {
#pragma unroll
    for (int o = 16; o > 0; o >>= 1) v = fmaxf(v, __shfl_xor_sync(0xffffffffu, v, o));
    return v;
}
__device__ float blockSum(float v) {
    __shared__ float s[33];
    int lane = threadIdx.x & 31, w = threadIdx.x >> 5;
    __syncthreads();
    v = warpSum(v);
    if (lane == 0) s[w] = v;
    __syncthreads();
    if (w == 0) {
        float t = (threadIdx.x < (blockDim.x >> 5)) ? s[threadIdx.x] : 0.f;
        t = warpSum(t);
        if (lane == 0) s[32] = t;
    }
    __syncthreads();
    return s[32];
}
__device__ float blockMax(float v) {
    __shared__ float s[33];
    int lane = threadIdx.x & 31, w = threadIdx.x >> 5;
    __syncthreads();
    v = warpMax(v);
    if (lane == 0) s[w] = v;
    __syncthreads();
    if (w == 0) {
        float t = (threadIdx.x < (blockDim.x >> 5)) ? s[threadIdx.x] : -INFINITY;
        t = warpMax(t);
        if (lane == 0) s[32] = t;
    }
    __syncthreads();
    return s[32];
}

// ---------------- K0: row squared norms (proven) ----------------
__global__ __launch_bounds__(256)
void norms_kernel(const float* __restrict__ gen, const float* __restrict__ pos) {
    int row = blockIdx.x;
    const float* src; float* dst;
    if (row < B_N) { src = gen + (size_t)row * D_N; dst = &g_gn[row]; }
    else           { src = pos + (size_t)(row - B_N) * D_N; dst = &g_pn[row - B_N]; }
    float s = 0.f;
    for (int c = threadIdx.x * 4; c < D_N; c += blockDim.x * 4) {
        float4 v = *(const float4*)(src + c);
        s += v.x * v.x + v.y * v.y + v.z * v.z + v.w * v.w;
    }
    s = blockSum(s);
    if (threadIdx.x == 0) *dst = s;
}

// ---------------- K1: fp16 hi/lo plane split (proven) ----------------
__global__ __launch_bounds__(256)
void split16(const float* __restrict__ gen, const float* __restrict__ pos) {
    const size_t total = (size_t)B_N * D_N;
    for (size_t idx = (size_t)blockIdx.x * blockDim.x + threadIdx.x; idx < total;
         idx += (size_t)gridDim.x * blockDim.x) {
        float x = gen[idx];
        __half h = __float2half(x);
        g_genH[idx] = h;
        g_genL[idx] = __float2half(x - __half2float(h));
        float y = pos[idx];
        __half hp = __float2half(y);
        g_posH[idx] = hp;
        g_posL[idx] = __float2half(y - __half2float(hp));
    }
}

// ---------------- K2: score GEMM, cp.async double-buffered (BK=32, 2 stages) ----------------
#define LDS32 40                   // padded smem stride in halves (32 + 8); 80B rows: conflict-free
#define TILE32 (128 * LDS32)       // 5120 halves per operand tile

__global__ __launch_bounds__(256)
void score_wmma(int b_is_gen) {
    __shared__ __align__(32) __half sh[4 * TILE32];   // [stage][A|B] = 40,960 B
    const int tid = threadIdx.x, lane = tid & 31, wid = tid >> 5;
    const int wm = (wid & 3) * 32, wn = (wid >> 2) * 64;
    const int m0 = blockIdx.y * 128, n0 = blockIdx.x * 128;

    const __half* segA[3] = { g_genH, g_genH, g_genL };
    const __half* segB[3];
    if (b_is_gen) { segB[0] = g_genH; segB[1] = g_genL; segB[2] = g_genH; }
    else          { segB[0] = g_posH; segB[1] = g_posL; segB[2] = g_posH; }

    const int NTSEG = D_N / 32;          // 32 k-tiles per segment
    const int NTT = 3 * NTSEG;           // 96 total (pipeline flattened across segments)

    auto issue = [&](int u, int s) {
        int seg = u / NTSEG, t = u - seg * NTSEG;
        const __half* A = segA[seg];
        const __half* B = segB[seg];
        __half* dA = sh + s * 2 * TILE32;
        __half* dB = dA + TILE32;
#pragma unroll
        for (int i = 0; i < 2; i++) {
            int f = i * 256 + tid, r = f >> 2, c = f & 3;
            __pipeline_memcpy_async(dA + r * LDS32 + c * 8,
                                    A + (size_t)(m0 + r) * D_N + t * 32 + c * 8, 16);
            __pipeline_memcpy_async(dB + r * LDS32 + c * 8,
                                    B + (size_t)(n0 + r) * D_N + t * 32 + c * 8, 16);
        }
        __pipeline_commit();
    };

    wmma::fragment<wmma::accumulator, 16, 16, 16, float> cfr[2][4];
#pragma unroll
    for (int i = 0; i < 2; i++)
#pragma unroll
        for (int j = 0; j < 4; j++) wmma::fill_fragment(cfr[i][j], 0.f);

    issue(0, 0);
    for (int u = 0; u < NTT; u++) {
        if (u + 1 < NTT) { issue(u + 1, (u + 1) & 1); __pipeline_wait_prior(1); }
        else             { __pipeline_wait_prior(0); }
        __syncthreads();
        const __half* bufA = sh + (u & 1) * 2 * TILE32;
        const __half* bufB = bufA + TILE32;
#pragma unroll
        for (int ks = 0; ks < 2; ks++) {
            wmma::fragment<wmma::matrix_a, 16, 16, 16, __half, wmma::row_major> afr[2];
            wmma::fragment<wmma::matrix_b, 16, 16, 16, __half, wmma::col_major> bfr[4];
#pragma unroll
            for (int i = 0; i < 2; i++)
                wmma::load_matrix_sync(afr[i], bufA + (wm + i * 16) * LDS32 + ks * 16, LDS32);
#pragma unroll
            for (int j = 0; j < 4; j++)
                wmma::load_matrix_sync(bfr[j], bufB + (wn + j * 16) * LDS32 + ks * 16, LDS32);
#pragma unroll
            for (int i = 0; i < 2; i++)
#pragma unroll
                for (int j = 0; j < 4; j++)
                    wmma::mma_sync(cfr[i][j], afr[i], bfr[j], cfr[i][j]);
        }
        __syncthreads();   // all warps done with buf u before iter u+1 issues into it
    }

    // epilogue (proven)
    float* patch = ((float*)sh) + wid * 256;
    const float* bnp = b_is_gen ? g_gn : g_pn;
#pragma unroll
    for (int i = 0; i < 2; i++) {
#pragma unroll
        for (int j = 0; j < 4; j++) {
            wmma::store_matrix_sync(patch, cfr[i][j], 16, wmma::mem_row_major);
            __syncwarp();
            const int pr = lane >> 1, pc = (lane & 1) * 8;
            const int row = m0 + wm + i * 16 + pr;
            const int colb = n0 + wn + j * 16 + pc;
            const float an = g_gn[row];
            float4 bn0 = *(const float4*)(bnp + colb);
            float4 bn1 = *(const float4*)(bnp + colb + 4);
            const float* p = patch + pr * 16 + pc;
            float bns[8] = {bn0.x, bn0.y, bn0.z, bn0.w, bn1.x, bn1.y, bn1.z, bn1.w};
            float o[8];
#pragma unroll
            for (int e = 0; e < 8; e++) {
                float d2 = fmaxf(an + bns[e] - 2.f * p[e], 0.f);
                o[e] = -10.f * sqrtf(d2);
            }
            float* dst = g_S + (size_t)row * B_N + colb;
            *(float4*)dst       = make_float4(o[0], o[1], o[2], o[3]);
            *(float4*)(dst + 4) = make_float4(o[4], o[5], o[6], o[7]);
            __syncwarp();
        }
    }
}

// ---------------- K3: row softmax -> fp16 hi/lo weight planes in place (proven) ----------------
__global__ __launch_bounds__(256)
void softmax_w16(int mask_diag) {
    __shared__ float sm[B_N];
    int row = blockIdx.x;
    const float* Srow = g_S + (size_t)row * B_N;
    float mx = -INFINITY;
    for (int j = threadIdx.x; j < B_N; j += blockDim.x) {
        float v = Srow[j];
        if (mask_diag && j == row) v = -INFINITY;
        sm[j] = v;
        mx = fmaxf(mx, v);
    }
    mx = blockMax(mx);
    float sum = 0.f;
    for (int j = threadIdx.x; j < B_N; j += blockDim.x) {
        float e = expf(sm[j] - mx);
        sm[j] = e;
        sum += e;
    }
    sum = blockSum(sum);
    float inv = 1.f / sum;
    __syncthreads();
    __half* WH = (__half*)g_S + (size_t)row * (2 * B_N);
    __half* WL = WH + B_N;
    for (int j = threadIdx.x; j < B_N; j += blockDim.x) {
        float w = sm[j] * inv;
        __half h = __float2half(w);
        WH[j] = h;
        WL[j] = __float2half(w - __half2float(h));
    }
}

// ---------------- K4: wavg GEMM (flipped, proven) + cp.async double buffering ----------------
// out[m][nn] = sum_k W[m][k] * P[k][nn]
//   matrix_a (2 frags) = P^T: col_major from smem [k][nn] tile, ld LDSP
//   matrix_b (4 frags) = W^T: col_major from smem [m][k] tile, ld LDS32 (proven fast path)
#define LDSP 136
#define WTILE (128 * LDS32)     // 5120 halves
#define PTILE (32 * LDSP)       // 4352 halves

__global__ __launch_bounds__(256)
void wavg_wmma(const float* __restrict__ sub, int to_rep) {
    __shared__ __align__(32) __half shW[2 * WTILE];   // 20,480 B
    __shared__ __align__(32) __half shP[2 * PTILE];   // 17,408 B

    const int tid = threadIdx.x, lane = tid & 31, wid = tid >> 5;
    const int w_nn = (wid & 3) * 32;     // nn (D) direction: 4 warps
    const int w_m  = (wid >> 2) * 64;    // m  (B) direction: 2 warps
    const int n0 = blockIdx.x * 128;     // D blocks (8), fastest -> consecutive CTAs share W tiles in L2
    const int m0 = blockIdx.y * 128;     // B blocks (64)

    const __half* WHp = (const __half*)g_S;
    const __half* WLp = (const __half*)g_S + B_N;
    const __half* segW[3] = { WHp, WHp, WLp };
    const __half* segP[3];
    if (to_rep) { segP[0] = g_genH; segP[1] = g_genL; segP[2] = g_genH; }
    else        { segP[0] = g_posH; segP[1] = g_posL; segP[2] = g_posH; }

    const int NTSEG = B_N / 32;          // 256 k-tiles per segment
    const int NTT = 3 * NTSEG;           // 768 total

    auto issue = [&](int u, int s) {
        int seg = u / NTSEG, t = u - seg * NTSEG;
        const __half* Wp = segW[seg];
        const __half* Pp = segP[seg];
        __half* dW = shW + s * WTILE;
        __half* dP = shP + s * PTILE;
#pragma unroll
        for (int i = 0; i < 2; i++) {
            int f = i * 256 + tid;
            int rw = f >> 2, cw = f & 3;                 // W: 128 rows x 2 chunks... 4 chunks/row
            __pipeline_memcpy_async(dW + rw * LDS32 + cw * 8,
                                    Wp + (size_t)(m0 + rw) * (2 * B_N) + t * 32 + cw * 8, 16);
            int rp = f >> 4, cp = f & 15;                // P: 32 rows x 16 chunks
            __pipeline_memcpy_async(dP + rp * LDSP + cp * 8,
                                    Pp + (size_t)(t * 32 + rp) * D_N + n0 + cp * 8, 16);
        }
        __pipeline_commit();
    };

    wmma::fragment<wmma::accumulator, 16, 16, 16, float> cfr[2][4];   // [nn][m]
#pragma unroll
    for (int i = 0; i < 2; i++)
#pragma unroll
        for (int j = 0; j < 4; j++) wmma::fill_fragment(cfr[i][j], 0.f);

    issue(0, 0);
    for (int u = 0; u < NTT; u++) {
        if (u + 1 < NTT) { issue(u + 1, (u + 1) & 1); __pipeline_wait_prior(1); }
        else             { __pipeline_wait_prior(0); }
        __syncthreads();
        const __half* bufW = shW + (u & 1) * WTILE;
        const __half* bufP = shP + (u & 1) * PTILE;
#pragma unroll
        for (int ks = 0; ks < 2; ks++) {
            wmma::fragment<wmma::matrix_a, 16, 16, 16, __half, wmma::col_major> afr[2];
            wmma::fragment<wmma::matrix_b, 16, 16, 16, __half, wmma::col_major> bfr[4];
#pragma unroll
            for (int i = 0; i < 2; i++)   // P^T (nn,k): origin bufP[k*LDSP + nn]
                wmma::load_matrix_sync(afr[i], bufP + (ks * 16) * LDSP + w_nn + i * 16, LDSP);
#pragma unroll
            for (int j = 0; j < 4; j++)   // W^T (k,m): origin bufW[m*LDS32 + k]
                wmma::load_matrix_sync(bfr[j], bufW + (w_m + j * 16) * LDS32 + ks * 16, LDS32);
#pragma unroll
            for (int i = 0; i < 2; i++)
#pragma unroll
                for (int j = 0; j < 4; j++)
                    wmma::mma_sync(cfr[i][j], afr[i], bfr[j], cfr[i][j]);
        }
        __syncthreads();
    }

    // epilogue (proven): cfr[i][j] is 16(nn) x 16(m); col_major store -> patch[m_local*16 + nn_local]
    float* outp = to_rep ? g_rep : g_attr;
    float* patch = ((float*)shW) + wid * 256;
#pragma unroll
    for (int i = 0; i < 2; i++) {
#pragma unroll
        for (int j = 0; j < 4; j++) {
            wmma::store_matrix_sync(patch, cfr[i][j], 16, wmma::mem_col_major);
            __syncwarp();
            const int pr = lane >> 1, pc = (lane & 1) * 8;     // pr = m_local, pc = nn_local base
            const int m  = m0 + w_m + j * 16 + pr;
            const int nn = n0 + w_nn + i * 16 + pc;
            const float* p = patch + pr * 16 + pc;
            size_t base = (size_t)m * D_N + nn;
            float4 s0 = *(const float4*)(sub + base);
            float4 s1 = *(const float4*)(sub + base + 4);
            *(float4*)(outp + base)     = make_float4(p[0] - s0.x, p[1] - s0.y,
                                                      p[2] - s0.z, p[3] - s0.w);
            *(float4*)(outp + base + 4) = make_float4(p[4] - s1.x, p[5] - s1.y,
                                                      p[6] - s1.z, p[7] - s1.w);
            __syncwarp();
        }
    }
}

// ---------------- K5/K6: final reductions (proven) ----------------
__global__ __launch_bounds__(256)
void row_reduce() {
    int row = blockIdx.x;
    const float* a = g_attr + (size_t)row * D_N;
    const float* r = g_rep + (size_t)row * D_N;
    float sa = 0.f, sr = 0.f, sd = 0.f;
    for (int c = threadIdx.x * 4; c < D_N; c += blockDim.x * 4) {
        float4 av = *(const float4*)(a + c);
        float4 rv = *(const float4*)(r + c);
        float dx = av.x - rv.x, dy = av.y - rv.y, dz = av.z - rv.z, dw = av.w - rv.w;
        sa += av.x * av.x + av.y * av.y + av.z * av.z + av.w * av.w;
        sr += rv.x * rv.x + rv.y * rv.y + rv.z * rv.z + rv.w * rv.w;
        sd += dx * dx + dy * dy + dz * dz + dw * dw;
    }
    sa = blockSum(sa); sr = blockSum(sr); sd = blockSum(sd);
    if (threadIdx.x == 0) {
        g_part[row * 4 + 0] = sd;
        g_part[row * 4 + 1] = sqrtf(sd);
        g_part[row * 4 + 2] = sqrtf(sa);
        g_part[row * 4 + 3] = sqrtf(sr);
    }
}

__global__ __launch_bounds__(256)
void final_reduce(float* __restrict__ out) {
    float s0 = 0.f, s1 = 0.f, s2 = 0.f, s3 = 0.f;
    for (int i = threadIdx.x; i < B_N; i += blockDim.x) {
        s0 += g_part[i * 4 + 0]; s1 += g_part[i * 4 + 1];
        s2 += g_part[i * 4 + 2]; s3 += g_part[i * 4 + 3];
    }
    s0 = blockSum(s0); s1 = blockSum(s1); s2 = blockSum(s2); s3 = blockSum(s3);
    if (threadIdx.x == 0) {
        out[0] = s0 / ((float)B_N * (float)D_N);
        out[1] = s1 / (float)B_N;
        out[2] = s2 / (float)B_N;
        out[3] = s3 / (float)B_N;
    }
}

// ---------------- launch ----------------
extern "C" void kernel_launch(void* const* d_in, const int* in_sizes, int n_in,
                              void* d_out, int out_size) {
    const float* gen = (const float*)d_in[0];
    const float* pos = (const float*)d_in[1];
    float* out = (float*)d_out;

    norms_kernel<<<2 * B_N, 256>>>(gen, pos);
    split16<<<4096, 256>>>(gen, pos);

    // Attraction: scores(gen,pos) -> softmax(W in place) -> W@pos - gen
    score_wmma<<<dim3(64, 64), 256>>>(0);
    softmax_w16<<<B_N, 256>>>(0);
    wavg_wmma<<<dim3(8, 64), 256>>>(gen, 0);

    // Repulsion: scores(gen,gen) diag-masked -> softmax -> W@gen - gen
    score_wmma<<<dim3(64, 64), 256>>>(1);
    softmax_w16<<<B_N, 256>>>(1);
    wavg_wmma<<<dim3(8, 64), 256>>>(gen, 1);

    row_reduce<<<B_N, 256>>>();
    final_reduce<<<1, 256>>>(out);
}

// round 12
// speedup vs baseline: 2.0617x; 1.1477x over previous
#include <cuda_runtime.h>
#include <cuda_fp16.h>
#include <cuda_pipeline.h>
#include <mma.h>
#include <math.h>
#include <stdint.h>

using namespace nvcuda;

// Problem constants (B=8192, B_pos=8192, D=1024, T=0.1)
#define B_N 8192
#define D_N 1024

// ---------------- scratch: EXACTLY the proven 384 MB set ----------------
// g_S doubles as fp32 score matrix, then per-row fp16 weight planes in place:
//   row r as halves: (half*)g_S + r*2*B_N ; [0..B_N)=WH, [B_N..2*B_N)=WL
static __device__ __align__(256) float  g_S[(size_t)B_N * B_N];      // 256 MB
static __device__ __align__(256) __half g_genH[(size_t)B_N * D_N];   // 16 MB
static __device__ __align__(256) __half g_genL[(size_t)B_N * D_N];   // 16 MB
static __device__ __align__(256) __half g_posH[(size_t)B_N * D_N];   // 16 MB
static __device__ __align__(256) __half g_posL[(size_t)B_N * D_N];   // 16 MB
static __device__ __align__(256) float g_attr[(size_t)B_N * D_N];    // 32 MB
static __device__ __align__(256) float g_rep[(size_t)B_N * D_N];     // 32 MB
static __device__ float g_gn[B_N];
static __device__ float g_pn[B_N];
static __device__ float g_part[B_N * 4];

// ---------------- reductions (proven) ----------------
__device__ __forceinline__ float warpSum(float v) {
#pragma unroll
    for (int o = 16; o > 0; o >>= 1) v += __shfl_xor_sync(0xffffffffu, v, o);
    return v;
}
__device__ __forceinline__ float warpMax(float v) {
#pragma unroll
    for (int o = 16; o > 0; o >>= 1) v = fmaxf(v, __shfl_xor_sync(0xffffffffu, v, o));
    return v;
}
__device__ float blockSum(float v) {
    __shared__ float s[33];
    int lane = threadIdx.x & 31, w = threadIdx.x >> 5;
    __syncthreads();
    v = warpSum(v);
    if (lane == 0) s[w] = v;
    __syncthreads();
    if (w == 0) {
        float t = (threadIdx.x < (blockDim.x >> 5)) ? s[threadIdx.x] : 0.f;
        t = warpSum(t);
        if (lane == 0) s[32] = t;
    }
    __syncthreads();
    return s[32];
}
__device__ float blockMax(float v) {
    __shared__ float s[33];
    int lane = threadIdx.x & 31, w = threadIdx.x >> 5;
    __syncthreads();
    v = warpMax(v);
    if (lane == 0) s[w] = v;
    __syncthreads();
    if (w == 0) {
        float t = (threadIdx.x < (blockDim.x >> 5)) ? s[threadIdx.x] : -INFINITY;
        t = warpMax(t);
        if (lane == 0) s[32] = t;
    }
    __syncthreads();
    return s[32];
}

// ---------------- K0: fused row norms + fp16 hi/lo plane split ----------------
__global__ __launch_bounds__(256)
void prep_kernel(const float* __restrict__ gen, const float* __restrict__ pos) {
    int row = blockIdx.x;
    const float* src; __half *H, *L; float* dst;
    if (row < B_N) {
        src = gen + (size_t)row * D_N;
        H = g_genH + (size_t)row * D_N; L = g_genL + (size_t)row * D_N;
        dst = &g_gn[row];
    } else {
        int r = row - B_N;
        src = pos + (size_t)r * D_N;
        H = g_posH + (size_t)r * D_N; L = g_posL + (size_t)r * D_N;
        dst = &g_pn[r];
    }
    float s = 0.f;
    for (int c = threadIdx.x * 4; c < D_N; c += blockDim.x * 4) {
        float4 v = *(const float4*)(src + c);
        s += v.x * v.x + v.y * v.y + v.z * v.z + v.w * v.w;
        __half hx = __float2half(v.x), hy = __float2half(v.y);
        __half hz = __float2half(v.z), hw = __float2half(v.w);
        __half2 h01 = __halves2half2(hx, hy), h23 = __halves2half2(hz, hw);
        __half2 l01 = __halves2half2(__float2half(v.x - __half2float(hx)),
                                     __float2half(v.y - __half2float(hy)));
        __half2 l23 = __halves2half2(__float2half(v.z - __half2float(hz)),
                                     __float2half(v.w - __half2float(hw)));
        *(__half2*)(H + c) = h01; *(__half2*)(H + c + 2) = h23;
        *(__half2*)(L + c) = l01; *(__half2*)(L + c + 2) = l23;
    }
    s = blockSum(s);
    if (threadIdx.x == 0) *dst = s;
}

// ---------------- K1: score GEMM, 4 warps, warp tile 64x64, cp.async 2-stage BK=32 ----------------
#define LDS32 40                   // padded smem stride in halves (32 + 8)
#define TILE32 (128 * LDS32)       // 5120 halves per operand tile

__global__ __launch_bounds__(128)
void score_wmma(int b_is_gen) {
    __shared__ __align__(32) __half sh[4 * TILE32];   // 40,960 B
    const int tid = threadIdx.x, lane = tid & 31, wid = tid >> 5;
    const int wm = (wid & 1) * 64, wn = (wid >> 1) * 64;   // 2x2 warp grid, 64x64 tiles
    const int m0 = blockIdx.y * 128, n0 = blockIdx.x * 128;

    const __half* segA[3] = { g_genH, g_genH, g_genL };
    const __half* segB[3];
    if (b_is_gen) { segB[0] = g_genH; segB[1] = g_genL; segB[2] = g_genH; }
    else          { segB[0] = g_posH; segB[1] = g_posL; segB[2] = g_posH; }

    const int NTSEG = D_N / 32;          // 32 k-tiles per segment
    const int NTT = 3 * NTSEG;           // 96

    auto issue = [&](int u, int s) {
        int seg = u / NTSEG, t = u - seg * NTSEG;
        const __half* A = segA[seg];
        const __half* B = segB[seg];
        __half* dA = sh + s * 2 * TILE32;
        __half* dB = dA + TILE32;
#pragma unroll
        for (int i = 0; i < 4; i++) {    // 128 rows x 4 chunks = 512 / 128 thr = 4 iters
            int f = i * 128 + tid, r = f >> 2, c = f & 3;
            __pipeline_memcpy_async(dA + r * LDS32 + c * 8,
                                    A + (size_t)(m0 + r) * D_N + t * 32 + c * 8, 16);
            __pipeline_memcpy_async(dB + r * LDS32 + c * 8,
                                    B + (size_t)(n0 + r) * D_N + t * 32 + c * 8, 16);
        }
        __pipeline_commit();
    };

    wmma::fragment<wmma::accumulator, 16, 16, 16, float> cfr[4][4];
#pragma unroll
    for (int i = 0; i < 4; i++)
#pragma unroll
        for (int j = 0; j < 4; j++) wmma::fill_fragment(cfr[i][j], 0.f);

    issue(0, 0);
    for (int u = 0; u < NTT; u++) {
        if (u + 1 < NTT) { issue(u + 1, (u + 1) & 1); __pipeline_wait_prior(1); }
        else             { __pipeline_wait_prior(0); }
        __syncthreads();
        const __half* bufA = sh + (u & 1) * 2 * TILE32;
        const __half* bufB = bufA + TILE32;
#pragma unroll
        for (int ks = 0; ks < 2; ks++) {
            wmma::fragment<wmma::matrix_a, 16, 16, 16, __half, wmma::row_major> afr[4];
            wmma::fragment<wmma::matrix_b, 16, 16, 16, __half, wmma::col_major> bfr[4];
#pragma unroll
            for (int i = 0; i < 4; i++)
                wmma::load_matrix_sync(afr[i], bufA + (wm + i * 16) * LDS32 + ks * 16, LDS32);
#pragma unroll
            for (int j = 0; j < 4; j++)
                wmma::load_matrix_sync(bfr[j], bufB + (wn + j * 16) * LDS32 + ks * 16, LDS32);
#pragma unroll
            for (int i = 0; i < 4; i++)
#pragma unroll
                for (int j = 0; j < 4; j++)
                    wmma::mma_sync(cfr[i][j], afr[i], bfr[j], cfr[i][j]);
        }
        __syncthreads();
    }

    // epilogue
    float* patch = ((float*)sh) + wid * 256;
    const float* bnp = b_is_gen ? g_gn : g_pn;
#pragma unroll
    for (int i = 0; i < 4; i++) {
#pragma unroll
        for (int j = 0; j < 4; j++) {
            wmma::store_matrix_sync(patch, cfr[i][j], 16, wmma::mem_row_major);
            __syncwarp();
            const int pr = lane >> 1, pc = (lane & 1) * 8;
            const int row = m0 + wm + i * 16 + pr;
            const int colb = n0 + wn + j * 16 + pc;
            const float an = g_gn[row];
            float4 bn0 = *(const float4*)(bnp + colb);
            float4 bn1 = *(const float4*)(bnp + colb + 4);
            const float* p = patch + pr * 16 + pc;
            float bns[8] = {bn0.x, bn0.y, bn0.z, bn0.w, bn1.x, bn1.y, bn1.z, bn1.w};
            float o[8];
#pragma unroll
            for (int e = 0; e < 8; e++) {
                float d2 = fmaxf(an + bns[e] - 2.f * p[e], 0.f);
                o[e] = -10.f * sqrtf(d2);
            }
            float* dst = g_S + (size_t)row * B_N + colb;
            *(float4*)dst       = make_float4(o[0], o[1], o[2], o[3]);
            *(float4*)(dst + 4) = make_float4(o[4], o[5], o[6], o[7]);
            __syncwarp();
        }
    }
}

// ---------------- K2: row softmax -> fp16 hi/lo weight planes in place (proven) ----------------
__global__ __launch_bounds__(256)
void softmax_w16(int mask_diag) {
    __shared__ float sm[B_N];
    int row = blockIdx.x;
    const float* Srow = g_S + (size_t)row * B_N;
    float mx = -INFINITY;
    for (int j = threadIdx.x; j < B_N; j += blockDim.x) {
        float v = Srow[j];
        if (mask_diag && j == row) v = -INFINITY;
        sm[j] = v;
        mx = fmaxf(mx, v);
    }
    mx = blockMax(mx);
    float sum = 0.f;
    for (int j = threadIdx.x; j < B_N; j += blockDim.x) {
        float e = expf(sm[j] - mx);
        sm[j] = e;
        sum += e;
    }
    sum = blockSum(sum);
    float inv = 1.f / sum;
    __syncthreads();
    __half* WH = (__half*)g_S + (size_t)row * (2 * B_N);
    __half* WL = WH + B_N;
    for (int j = threadIdx.x; j < B_N; j += blockDim.x) {
        float w = sm[j] * inv;
        __half h = __float2half(w);
        WH[j] = h;
        WL[j] = __float2half(w - __half2float(h));
    }
}

// ---------------- K3: wavg GEMM (flipped), 4 warps, warp tile 64x64, cp.async 2-stage ----------------
// out[m][nn] = sum_k W[m][k] * P[k][nn]
//   matrix_a (4 frags) = P^T: col_major from smem [k][nn] tile, ld LDSP
//   matrix_b (4 frags) = W^T: col_major from smem [m][k] tile, ld LDS32
#define LDSP 136
#define WTILE (128 * LDS32)     // 5120 halves
#define PTILE (32 * LDSP)       // 4352 halves

__global__ __launch_bounds__(128)
void wavg_wmma(const float* __restrict__ sub, int to_rep) {
    __shared__ __align__(32) __half shW[2 * WTILE];   // 20,480 B
    __shared__ __align__(32) __half shP[2 * PTILE];   // 17,408 B

    const int tid = threadIdx.x, lane = tid & 31, wid = tid >> 5;
    const int w_nn = (wid & 1) * 64;     // nn (D): 2 warps x 64
    const int w_m  = (wid >> 1) * 64;    // m  (B): 2 warps x 64
    const int n0 = blockIdx.x * 128;     // D blocks (8), fastest -> W tiles L2-shared
    const int m0 = blockIdx.y * 128;     // B blocks (64)

    const __half* WHp = (const __half*)g_S;
    const __half* WLp = (const __half*)g_S + B_N;
    const __half* segW[3] = { WHp, WHp, WLp };
    const __half* segP[3];
    if (to_rep) { segP[0] = g_genH; segP[1] = g_genL; segP[2] = g_genH; }
    else        { segP[0] = g_posH; segP[1] = g_posL; segP[2] = g_posH; }

    const int NTSEG = B_N / 32;          // 256 k-tiles per segment
    const int NTT = 3 * NTSEG;           // 768

    auto issue = [&](int u, int s) {
        int seg = u / NTSEG, t = u - seg * NTSEG;
        const __half* Wp = segW[seg];
        const __half* Pp = segP[seg];
        __half* dW = shW + s * WTILE;
        __half* dP = shP + s * PTILE;
#pragma unroll
        for (int i = 0; i < 4; i++) {
            int f = i * 128 + tid;
            int rw = f >> 2, cw = f & 3;                 // W: 128 rows x 4 chunks
            __pipeline_memcpy_async(dW + rw * LDS32 + cw * 8,
                                    Wp + (size_t)(m0 + rw) * (2 * B_N) + t * 32 + cw * 8, 16);
            int rp = f >> 4, cp = f & 15;                // P: 32 rows x 16 chunks
            __pipeline_memcpy_async(dP + rp * LDSP + cp * 8,
                                    Pp + (size_t)(t * 32 + rp) * D_N + n0 + cp * 8, 16);
        }
        __pipeline_commit();
    };

    wmma::fragment<wmma::accumulator, 16, 16, 16, float> cfr[4][4];   // [nn][m]
#pragma unroll
    for (int i = 0; i < 4; i++)
#pragma unroll
        for (int j = 0; j < 4; j++) wmma::fill_fragment(cfr[i][j], 0.f);

    issue(0, 0);
    for (int u = 0; u < NTT; u++) {
        if (u + 1 < NTT) { issue(u + 1, (u + 1) & 1); __pipeline_wait_prior(1); }
        else             { __pipeline_wait_prior(0); }
        __syncthreads();
        const __half* bufW = shW + (u & 1) * WTILE;
        const __half* bufP = shP + (u & 1) * PTILE;
#pragma unroll
        for (int ks = 0; ks < 2; ks++) {
            wmma::fragment<wmma::matrix_a, 16, 16, 16, __half, wmma::col_major> afr[4];
            wmma::fragment<wmma::matrix_b, 16, 16, 16, __half, wmma::col_major> bfr[4];
#pragma unroll
            for (int i = 0; i < 4; i++)   // P^T (nn,k): origin bufP[k*LDSP + nn]
                wmma::load_matrix_sync(afr[i], bufP + (ks * 16) * LDSP + w_nn + i * 16, LDSP);
#pragma unroll
            for (int j = 0; j < 4; j++)   // W^T (k,m): origin bufW[m*LDS32 + k]
                wmma::load_matrix_sync(bfr[j], bufW + (w_m + j * 16) * LDS32 + ks * 16, LDS32);
#pragma unroll
            for (int i = 0; i < 4; i++)
#pragma unroll
                for (int j = 0; j < 4; j++)
                    wmma::mma_sync(cfr[i][j], afr[i], bfr[j], cfr[i][j]);
        }
        __syncthreads();
    }

    // epilogue: cfr[i][j] is 16(nn) x 16(m); col_major store -> patch[m_local*16 + nn_local]
    float* outp = to_rep ? g_rep : g_attr;
    float* patch = ((float*)shW) + wid * 256;
#pragma unroll
    for (int i = 0; i < 4; i++) {
#pragma unroll
        for (int j = 0; j < 4; j++) {
            wmma::store_matrix_sync(patch, cfr[i][j], 16, wmma::mem_col_major);
            __syncwarp();
            const int pr = lane >> 1, pc = (lane & 1) * 8;     // pr = m_local, pc = nn_local base
            const int m  = m0 + w_m + j * 16 + pr;
            const int nn = n0 + w_nn + i * 16 + pc;
            const float* p = patch + pr * 16 + pc;
            size_t base = (size_t)m * D_N + nn;
            float4 s0 = *(const float4*)(sub + base);
            float4 s1 = *(const float4*)(sub + base + 4);
            *(float4*)(outp + base)     = make_float4(p[0] - s0.x, p[1] - s0.y,
                                                      p[2] - s0.z, p[3] - s0.w);
            *(float4*)(outp + base + 4) = make_float4(p[4] - s1.x, p[5] - s1.y,
                                                      p[6] - s1.z, p[7] - s1.w);
            __syncwarp();
        }
    }
}

// ---------------- K4/K5: final reductions (proven) ----------------
__global__ __launch_bounds__(256)
void row_reduce() {
    int row = blockIdx.x;
    const float* a = g_attr + (size_t)row * D_N;
    const float* r = g_rep + (size_t)row * D_N;
    float sa = 0.f, sr = 0.f, sd = 0.f;
    for (int c = threadIdx.x * 4; c < D_N; c += blockDim.x * 4) {
        float4 av = *(const float4*)(a + c);
        float4 rv = *(const float4*)(r + c);
        float dx = av.x - rv.x, dy = av.y - rv.y, dz = av.z - rv.z, dw = av.w - rv.w;
        sa += av.x * av.x + av.y * av.y + av.z * av.z + av.w * av.w;
        sr += rv.x * rv.x + rv.y * rv.y + rv.z * rv.z + rv.w * rv.w;
        sd += dx * dx + dy * dy + dz * dz + dw * dw;
    }
    sa = blockSum(sa); sr = blockSum(sr); sd = blockSum(sd);
    if (threadIdx.x == 0) {
        g_part[row * 4 + 0] = sd;
        g_part[row * 4 + 1] = sqrtf(sd);
        g_part[row * 4 + 2] = sqrtf(sa);
        g_part[row * 4 + 3] = sqrtf(sr);
    }
}

__global__ __launch_bounds__(256)
void final_reduce(float* __restrict__ out) {
    float s0 = 0.f, s1 = 0.f, s2 = 0.f, s3 = 0.f;
    for (int i = threadIdx.x; i < B_N; i += blockDim.x) {
        s0 += g_part[i * 4 + 0]; s1 += g_part[i * 4 + 1];
        s2 += g_part[i * 4 + 2]; s3 += g_part[i * 4 + 3];
    }
    s0 = blockSum(s0); s1 = blockSum(s1); s2 = blockSum(s2); s3 = blockSum(s3);
    if (threadIdx.x == 0) {
        out[0] = s0 / ((float)B_N * (float)D_N);
        out[1] = s1 / (float)B_N;
        out[2] = s2 / (float)B_N;
        out[3] = s3 / (float)B_N;
    }
}

// ---------------- launch ----------------
extern "C" void kernel_launch(void* const* d_in, const int* in_sizes, int n_in,
                              void* d_out, int out_size) {
    const float* gen = (const float*)d_in[0];
    const float* pos = (const float*)d_in[1];
    float* out = (float*)d_out;

    prep_kernel<<<2 * B_N, 256>>>(gen, pos);

    // Attraction: scores(gen,pos) -> softmax(W in place) -> W@pos - gen
    score_wmma<<<dim3(64, 64), 128>>>(0);
    softmax_w16<<<B_N, 256>>>(0);
    wavg_wmma<<<dim3(8, 64), 128>>>(gen, 0);

    // Repulsion: scores(gen,gen) diag-masked -> softmax -> W@gen - gen
    score_wmma<<<dim3(64, 64), 128>>>(1);
    softmax_w16<<<B_N, 256>>>(1);
    wavg_wmma<<<dim3(8, 64), 128>>>(gen, 1);

    row_reduce<<<B_N, 256>>>();
    final_reduce<<<1, 256>>>(out);
}